// round 5
// baseline (speedup 1.0000x reference)
#include <cuda_runtime.h>
#include <cuda_bf16.h>

// ---------------------------------------------------------------------------
// CFConv: f = x @ W_in ; wf = w_ij * f[idx_j] ; conv = segment_sum(wf, seg_i)
//         out = conv @ W_out + b_out
// Shapes: x[20000,128], w_ij[640000,128], seg_i/idx_j[640000] (seg_i sorted),
//         W_in/W_out[128,128], b_out[128]. All fp32.
//
// kernel_launch performs ONLY kernel launches. Scratch in __device__ globals.
// All shared memory static and <= 48 KB.
// ---------------------------------------------------------------------------

#define NFM 128
#define N_ATOMS_MAX 20000

__device__ float g_f[N_ATOMS_MAX * NFM];     // f = x @ W_in
__device__ float g_conv[N_ATOMS_MAX * NFM];  // segment-sum accumulator

// ---------------------------------------------------------------------------
// GEMM: C[n,128] = A[n,128] @ W[128,128] (+ bias).
// mode 0: A = A_ext,  C = g_f,   zero g_conv rows alongside the store.
// mode 1: A = g_conv, C = C_ext, add bias.
// 256 threads, 128 rows x 128 cols per block, K in 4 phases of 32.
// Per-thread 8x8 outer-product micro-tile: 4 LDS.128 + 64 FFMA per K-step.
// A is stored TRANSPOSED in smem (Xs[k][row]) so a-operands are float4 loads.
// ---------------------------------------------------------------------------
#define KB 32

__global__ void __launch_bounds__(256, 2) gemm128_kernel(
    const float* __restrict__ A_ext, const float* __restrict__ W,
    const float* __restrict__ bias, float* __restrict__ C_ext,
    int mode, int n)
{
    __shared__ float Ws[KB * NFM];  // 16 KB: [k][col]
    __shared__ float Xs[KB * NFM];  // 16 KB: [k][row] (transposed A tile)

    const float* A = (mode == 1) ? g_conv : A_ext;
    float*       C = (mode == 1) ? C_ext  : g_f;

    const int tid  = threadIdx.x;
    const int row0 = blockIdx.x * 128;
    const int tx   = tid & 15;   // col group: cols tx*8 .. tx*8+7
    const int ty   = tid >> 4;   // row group: rows ty*8 .. ty*8+7

    float acc[8][8];
#pragma unroll
    for (int i = 0; i < 8; i++)
#pragma unroll
        for (int j = 0; j < 8; j++) acc[i][j] = 0.f;

#pragma unroll
    for (int kb = 0; kb < NFM; kb += KB) {
        // W rows kb..kb+31, all 128 cols: 1024 float4, 4 per thread
        {
            const float4* W4  = (const float4*)(W + (size_t)kb * NFM);
            float4*       Ws4 = (float4*)Ws;
#pragma unroll
            for (int t = 0; t < 4; t++) Ws4[tid + t * 256] = W4[tid + t * 256];
        }
        // A rows row0..row0+127, cols kb..kb+31, transposed into Xs[k][r].
        // slot -> (r = slot&127, kq = slot>>7); warp lanes get consecutive r
        // with the same kq -> conflict-free STS.32.
        {
#pragma unroll
            for (int t = 0; t < 4; t++) {
                int slot = tid + t * 256;      // 0..1023
                int r    = slot & 127;
                int kq   = slot >> 7;          // 0..7 (k quad)
                float4 v = make_float4(0.f, 0.f, 0.f, 0.f);
                if (row0 + r < n)
                    v = *(const float4*)&A[(size_t)(row0 + r) * NFM + kb + kq * 4];
                Xs[(kq * 4 + 0) * NFM + r] = v.x;
                Xs[(kq * 4 + 1) * NFM + r] = v.y;
                Xs[(kq * 4 + 2) * NFM + r] = v.z;
                Xs[(kq * 4 + 3) * NFM + r] = v.w;
            }
        }
        __syncthreads();

#pragma unroll 4
        for (int k = 0; k < KB; k++) {
            float4 a0 = *(const float4*)&Xs[k * NFM + ty * 8];
            float4 a1 = *(const float4*)&Xs[k * NFM + ty * 8 + 4];
            float4 b0 = *(const float4*)&Ws[k * NFM + tx * 8];
            float4 b1 = *(const float4*)&Ws[k * NFM + tx * 8 + 4];
            float a[8] = {a0.x, a0.y, a0.z, a0.w, a1.x, a1.y, a1.z, a1.w};
            float b[8] = {b0.x, b0.y, b0.z, b0.w, b1.x, b1.y, b1.z, b1.w};
#pragma unroll
            for (int i = 0; i < 8; i++)
#pragma unroll
                for (int j = 0; j < 8; j++)
                    acc[i][j] = fmaf(a[i], b[j], acc[i][j]);
        }
        __syncthreads();
    }

    float4 bb0 = make_float4(0.f, 0.f, 0.f, 0.f);
    float4 bb1 = make_float4(0.f, 0.f, 0.f, 0.f);
    if (mode == 1) {
        bb0 = *(const float4*)&bias[tx * 8];
        bb1 = *(const float4*)&bias[tx * 8 + 4];
    }

#pragma unroll
    for (int i = 0; i < 8; i++) {
        int r = row0 + ty * 8 + i;
        if (r < n) {
            float4 v0 = make_float4(acc[i][0] + bb0.x, acc[i][1] + bb0.y,
                                    acc[i][2] + bb0.z, acc[i][3] + bb0.w);
            float4 v1 = make_float4(acc[i][4] + bb1.x, acc[i][5] + bb1.y,
                                    acc[i][6] + bb1.z, acc[i][7] + bb1.w);
            *(float4*)&C[(size_t)r * NFM + tx * 8]     = v0;
            *(float4*)&C[(size_t)r * NFM + tx * 8 + 4] = v1;
            if (mode == 0) {
                *(float4*)&g_conv[(size_t)r * NFM + tx * 8] =
                    make_float4(0.f, 0.f, 0.f, 0.f);
                *(float4*)&g_conv[(size_t)r * NFM + tx * 8 + 4] =
                    make_float4(0.f, 0.f, 0.f, 0.f);
            }
        }
    }
}

// ---------------------------------------------------------------------------
// Edge kernel: each warp owns EPW contiguous edges (seg_i sorted). Lane l
// handles channels 4l..4l+3. Register accumulation per segment run; atomic
// flush only at segment boundaries / chunk ends. Unrolled x4 for MLP.
// ---------------------------------------------------------------------------
#define EPW 128

__device__ __forceinline__ void flush_seg(int seg, int c, float4& acc)
{
    atomicAdd(&g_conv[(size_t)seg * NFM + c + 0], acc.x);
    atomicAdd(&g_conv[(size_t)seg * NFM + c + 1], acc.y);
    atomicAdd(&g_conv[(size_t)seg * NFM + c + 2], acc.z);
    atomicAdd(&g_conv[(size_t)seg * NFM + c + 3], acc.w);
    acc = make_float4(0.f, 0.f, 0.f, 0.f);
}

__global__ void __launch_bounds__(256) edge_kernel(
    const float* __restrict__ w_ij, const int* __restrict__ seg_i,
    const int* __restrict__ idx_j, int n_edges)
{
    const int gw   = (blockIdx.x * blockDim.x + threadIdx.x) >> 5;
    const int lane = threadIdx.x & 31;
    long e0 = (long)gw * EPW;
    if (e0 >= n_edges) return;
    long e1 = e0 + EPW;
    if (e1 > n_edges) e1 = n_edges;

    const int c = lane * 4;
    float4 acc  = make_float4(0.f, 0.f, 0.f, 0.f);
    int cur     = seg_i[e0];

    long e = e0;
    for (; e + 4 <= e1; e += 4) {
        int s[4], j[4];
#pragma unroll
        for (int u = 0; u < 4; u++) {
            s[u] = seg_i[e + u];
            j[u] = idx_j[e + u];
        }
        float4 w[4], fj[4];
#pragma unroll
        for (int u = 0; u < 4; u++) {
            w[u]  = *(const float4*)&w_ij[(size_t)(e + u) * NFM + c];
            fj[u] = *(const float4*)&g_f[(size_t)j[u] * NFM + c];
        }
#pragma unroll
        for (int u = 0; u < 4; u++) {
            if (s[u] != cur) { flush_seg(cur, c, acc); cur = s[u]; }
            acc.x = fmaf(w[u].x, fj[u].x, acc.x);
            acc.y = fmaf(w[u].y, fj[u].y, acc.y);
            acc.z = fmaf(w[u].z, fj[u].z, acc.z);
            acc.w = fmaf(w[u].w, fj[u].w, acc.w);
        }
    }
    for (; e < e1; e++) {
        int s = seg_i[e];
        int j = idx_j[e];
        if (s != cur) { flush_seg(cur, c, acc); cur = s; }
        float4 w  = *(const float4*)&w_ij[(size_t)e * NFM + c];
        float4 fj = *(const float4*)&g_f[(size_t)j * NFM + c];
        acc.x = fmaf(w.x, fj.x, acc.x);
        acc.y = fmaf(w.y, fj.y, acc.y);
        acc.z = fmaf(w.z, fj.z, acc.z);
        acc.w = fmaf(w.w, fj.w, acc.w);
    }
    flush_seg(cur, c, acc);
}

// ---------------------------------------------------------------------------
// Launch. Inputs: x, w_ij, seg_i, idx_j, [seg_i_sum?], W_in, W_out, b_out.
// ---------------------------------------------------------------------------
extern "C" void kernel_launch(void* const* d_in, const int* in_sizes, int n_in,
                              void* d_out, int out_size)
{
    const float* x     = (const float*)d_in[0];
    const float* w_ij  = (const float*)d_in[1];
    const int*   seg_i = (const int*)d_in[2];
    const int*   idx_j = (const int*)d_in[3];

    int base = 4;
    if (base < n_in && in_sizes[base] == 1) base = 5;
    const float* W_in  = (const float*)d_in[base + 0];
    const float* W_out = (const float*)d_in[base + 1];
    const float* b_out = (const float*)d_in[base + 2];

    const int n_atoms = in_sizes[0] / NFM;
    const int n_edges = in_sizes[2];

    const int gblocks = (n_atoms + 127) / 128;

    // f = x @ W_in ; zero g_conv alongside
    gemm128_kernel<<<gblocks, 256>>>(x, W_in, nullptr, nullptr, 0, n_atoms);

    // g_conv += segment_sum(w_ij * g_f[idx_j])
    const int warps   = (n_edges + EPW - 1) / EPW;
    const int eblocks = (warps * 32 + 255) / 256;
    edge_kernel<<<eblocks, 256>>>(w_ij, seg_i, idx_j, n_edges);

    // out = g_conv @ W_out + b_out
    gemm128_kernel<<<gblocks, 256>>>(nullptr, W_out, b_out, (float*)d_out,
                                     1, n_atoms);
}